// round 14
// baseline (speedup 1.0000x reference)
#include <cuda_runtime.h>
#include <cuda_fp16.h>
#include <type_traits>

// Problem constants
#define BB   4
#define CC   192
#define C3   576
#define HGT  256
#define WID  256
#define HWS  65536
#define NH   4
#define DD   48
#define NCHUNK 32
#define CHL  (HWS / NCHUNK)   // 2048
#define NPART (NCHUNK * 8)    // 256 split-K partial slots

// Scratch (device globals)
__device__ __half g_wqh [C3 * CC];                // qkv_w in fp16
__device__ __half g_qkvh[(size_t)BB * C3 * HWS];  // 1x1 conv output (fp16)
__device__ __half g_dwh [(size_t)BB * C3 * HWS];  // dwconv output (fp16)
__device__ float  g_sqp[BB * C3][32];
__device__ float  g_sq [BB * 2 * CC];
__device__ float  g_part[(size_t)NPART * BB * NH * DD * DD];
__device__ float  g_S  [16 * DD * DD];            // reduced Gram
__device__ __half g_w2h[BB * CC * CC];            // fused proj @ attn, fp16

// ---------------------------------------------------------------------------
__device__ __forceinline__ unsigned pack_h2(float lo, float hi) {
    __half2 h = __halves2half2(__float2half_rn(lo), __float2half_rn(hi));
    return *(unsigned*)&h;
}

__device__ __forceinline__ void mma_fp16(float c[4], const unsigned a[4], const unsigned b[2]) {
    asm volatile(
        "mma.sync.aligned.m16n8k16.row.col.f32.f16.f16.f32 "
        "{%0,%1,%2,%3}, {%4,%5,%6,%7}, {%8,%9}, {%0,%1,%2,%3};"
        : "+f"(c[0]), "+f"(c[1]), "+f"(c[2]), "+f"(c[3])
        : "r"(a[0]), "r"(a[1]), "r"(a[2]), "r"(a[3]), "r"(b[0]), "r"(b[1]));
}

// no-op kernel: shifts subsequent launches into ncu's profiled (4th) slot
__global__ void noop_kernel() {}

// ---------------------------------------------------------------------------
// qkv_w (f32) -> fp16, identical rounding to the old in-GEMM cvt. 4/thread.
// ---------------------------------------------------------------------------
__global__ __launch_bounds__(256) void wq2h_kernel(const float* __restrict__ w)
{
    const int i = (blockIdx.x * 256 + threadIdx.x) * 4;
    float4 a = *(const float4*)(w + i);
    uint2 p;
    p.x = pack_h2(a.x, a.y);
    p.y = pack_h2(a.z, a.w);
    *(uint2*)(g_wqh + i) = p;
}

// ---------------------------------------------------------------------------
// Tensor-core GEMM, BM=96 x BN=256 block, 8 warps of 48x64 (2m x 4n).
//   C[M,N](CT) = A[M,K](half) @ B[K,N](BT), batch via grid.z, M % 96 == 0.
// Bigger warp tiles cut fragment-LDS bytes per output 24% vs the 64x256
// version (L1 wavefront bandwidth is the measured bottleneck).
// PD=1 for f32 B, PD=2 for fp16 B. Fully unrolled (K compile-time).
// Conflict-free smem (strides ≡ 8 mod 32).
// ---------------------------------------------------------------------------
struct BStageF { float4 v[4]; };
struct BStageH { uint2  v[4]; };

template <typename BT, typename CT, int K>
__global__ __launch_bounds__(256, 1) void gemm96_kernel(
    const __half* __restrict__ A, const BT* __restrict__ B, CT* __restrict__ C,
    int M, int N, long sA, long sB, long sC)
{
    constexpr int NT = K >> 4;                       // 12
    constexpr bool BF32 = (sizeof(BT) == 4);
    constexpr int PD = BF32 ? 1 : 2;                 // prefetch distance

    __shared__ unsigned Ap[2][8][96 + 8];            // stride 104 ≡ 8 (mod 32)
    __shared__ unsigned Bp[2][8][256 + 8];           // stride 264 ≡ 8 (mod 32)

    const __half* Ab = A + (long)blockIdx.z * sA;
    const BT*     Bb = B + (long)blockIdx.z * sB;
    CT*           Cb = C + (long)blockIdx.z * sC;

    const int m0 = blockIdx.x * 96;
    const int n0 = blockIdx.y * 256;
    const int t    = threadIdx.x;
    const int lane = t & 31;
    const int wid  = t >> 5;
    const int wm   = (wid & 1) * 48;
    const int wn   = (wid >> 1) * 64;
    const int g    = lane >> 2;
    const int tg   = lane & 3;

    float acc[3][8][4];
    #pragma unroll
    for (int mt = 0; mt < 3; mt++)
        #pragma unroll
        for (int nt = 0; nt < 8; nt++)
            #pragma unroll
            for (int i = 0; i < 4; i++) acc[mt][nt][i] = 0.f;

    // A stage: threads t<192, row = t>>1 (0..95), k8 = (t&1)*8
    const bool aact = (t < 192);
    const int  arow = t >> 1;
    const int  ak8  = (t & 1) * 8;
    // B stage: cols bn4 = (t&63)*4, rows 4*(t>>6) + 0..3; packed k2 = 2*(t>>6)
    const int bn4 = (t & 63) << 2;
    const int bk2 = (t >> 6) << 1;

    const __half* apt = Ab + (long)(m0 + arow) * K + ak8;
    const BT*     bpt = Bb + (long)(bk2 * 2) * N + n0 + bn4;

    uint4 pa[PD];
    using BS = typename std::conditional<BF32, BStageF, BStageH>::type;
    BS pb[PD];

    auto ldg_tile = [&](int kt, int s) {
        if (aact) pa[s] = *(const uint4*)(apt + kt * 16);
        const BT* bp = bpt + (long)kt * 16 * N;
        #pragma unroll
        for (int i = 0; i < 4; i++) {
            if constexpr (BF32) pb[s].v[i] = *(const float4*)(bp + (long)i * N);
            else                pb[s].v[i] = *(const uint2*) (bp + (long)i * N);
        }
    };

    auto sts_tile = [&](int s, int stage) {
        if (aact) {
            const int k2b = (t & 1) * 4;
            Ap[stage][k2b + 0][arow] = pa[s].x;
            Ap[stage][k2b + 1][arow] = pa[s].y;
            Ap[stage][k2b + 2][arow] = pa[s].z;
            Ap[stage][k2b + 3][arow] = pa[s].w;
        }
        uint4 u0, u1;
        if constexpr (BF32) {
            u0.x = pack_h2(pb[s].v[0].x, pb[s].v[1].x);
            u0.y = pack_h2(pb[s].v[0].y, pb[s].v[1].y);
            u0.z = pack_h2(pb[s].v[0].z, pb[s].v[1].z);
            u0.w = pack_h2(pb[s].v[0].w, pb[s].v[1].w);
            u1.x = pack_h2(pb[s].v[2].x, pb[s].v[3].x);
            u1.y = pack_h2(pb[s].v[2].y, pb[s].v[3].y);
            u1.z = pack_h2(pb[s].v[2].z, pb[s].v[3].z);
            u1.w = pack_h2(pb[s].v[2].w, pb[s].v[3].w);
        } else {
            u0.x = __byte_perm(pb[s].v[0].x, pb[s].v[1].x, 0x5410);
            u0.y = __byte_perm(pb[s].v[0].x, pb[s].v[1].x, 0x7632);
            u0.z = __byte_perm(pb[s].v[0].y, pb[s].v[1].y, 0x5410);
            u0.w = __byte_perm(pb[s].v[0].y, pb[s].v[1].y, 0x7632);
            u1.x = __byte_perm(pb[s].v[2].x, pb[s].v[3].x, 0x5410);
            u1.y = __byte_perm(pb[s].v[2].x, pb[s].v[3].x, 0x7632);
            u1.z = __byte_perm(pb[s].v[2].y, pb[s].v[3].y, 0x5410);
            u1.w = __byte_perm(pb[s].v[2].y, pb[s].v[3].y, 0x7632);
        }
        *(uint4*)&Bp[stage][bk2][bn4]     = u0;
        *(uint4*)&Bp[stage][bk2 + 1][bn4] = u1;
    };

    // prologue
    ldg_tile(0, 0);
    sts_tile(0, 0);
    if constexpr (PD == 2) ldg_tile(1, 1);
    __syncthreads();

    #pragma unroll
    for (int kt = 0; kt < NT; kt++) {
        const int cur = kt & 1;

        if (kt + PD < NT) ldg_tile(kt + PD, (kt + PD) % PD);

        unsigned af[3][4];
        #pragma unroll
        for (int mt = 0; mt < 3; mt++) {
            int mb = wm + mt * 16 + g;
            af[mt][0] = Ap[cur][tg][mb];
            af[mt][1] = Ap[cur][tg][mb + 8];
            af[mt][2] = Ap[cur][tg + 4][mb];
            af[mt][3] = Ap[cur][tg + 4][mb + 8];
        }
        #pragma unroll
        for (int nt = 0; nt < 8; nt++) {
            int nb = wn + nt * 8 + g;
            unsigned bf[2];
            bf[0] = Bp[cur][tg][nb];
            bf[1] = Bp[cur][tg + 4][nb];
            #pragma unroll
            for (int mt = 0; mt < 3; mt++)
                mma_fp16(acc[mt][nt], af[mt], bf);
        }

        if (kt + 1 < NT) sts_tile((kt + 1) % PD, cur ^ 1);
        __syncthreads();
    }

    #pragma unroll
    for (int mt = 0; mt < 3; mt++) {
        #pragma unroll
        for (int nt = 0; nt < 8; nt++) {
            int row = m0 + wm + mt * 16 + g;
            int col = n0 + wn + nt * 8 + 2 * tg;
            if constexpr (sizeof(CT) == 2) {
                *(unsigned*)((__half*)Cb + (long)row * N + col) =
                    pack_h2(acc[mt][nt][0], acc[mt][nt][1]);
                *(unsigned*)((__half*)Cb + (long)(row + 8) * N + col) =
                    pack_h2(acc[mt][nt][2], acc[mt][nt][3]);
            } else {
                *(float2*)((float*)Cb + (long)row * N + col) =
                    make_float2(acc[mt][nt][0], acc[mt][nt][1]);
                *(float2*)((float*)Cb + (long)(row + 8) * N + col) =
                    make_float2(acc[mt][nt][2], acc[mt][nt][3]);
            }
        }
    }
}

// ---------------------------------------------------------------------------
// Depthwise 3x3 conv v5: warp covers a full 256-px row (8 px/lane, LDG.128),
// x-halo via 2 warp shuffles; fp32 math; fused sumsq.
// grid (1, 4, BB*C3), block 256.
// ---------------------------------------------------------------------------
__global__ __launch_bounds__(256) void dwconv_kernel(const float* __restrict__ w)
{
    const int bc = blockIdx.z;
    const int c  = bc % C3;
    const __half* plane = g_qkvh + (size_t)bc * HWS;
    __half*       op    = g_dwh  + (size_t)bc * HWS;

    float wr[9];
    #pragma unroll
    for (int i = 0; i < 9; i++) wr[i] = w[c * 9 + i];

    const int t    = threadIdx.x;
    const int lane = t & 31;
    const int wp   = t >> 5;
    const int y0   = blockIdx.y * 64 + wp * 8;
    const int x0   = lane * 8;

    float o[8][8];
    #pragma unroll
    for (int i = 0; i < 8; i++)
        #pragma unroll
        for (int j = 0; j < 8; j++) o[i][j] = 0.f;

    #pragma unroll
    for (int i = -1; i <= 8; i++) {
        const int r = y0 + i;
        float m[8];
        if (r >= 0 && r < HGT) {
            uint4 v = *(const uint4*)(plane + (size_t)r * WID + x0);
            float2 f;
            f = __half22float2(*(__half2*)&v.x); m[0] = f.x; m[1] = f.y;
            f = __half22float2(*(__half2*)&v.y); m[2] = f.x; m[3] = f.y;
            f = __half22float2(*(__half2*)&v.z); m[4] = f.x; m[5] = f.y;
            f = __half22float2(*(__half2*)&v.w); m[6] = f.x; m[7] = f.y;
        } else {
            #pragma unroll
            for (int j = 0; j < 8; j++) m[j] = 0.f;
        }
        float lh = __shfl_up_sync(0xffffffffu,  m[7], 1);
        float rh = __shfl_down_sync(0xffffffffu, m[0], 1);
        if (lane == 0)  lh = 0.f;
        if (lane == 31) rh = 0.f;

        float L[8], R[8];
        L[0] = lh;
        #pragma unroll
        for (int j = 1; j < 8; j++) L[j] = m[j - 1];
        #pragma unroll
        for (int j = 0; j < 7; j++) R[j] = m[j + 1];
        R[7] = rh;

        if (i + 1 >= 0 && i + 1 < 8) {
            #pragma unroll
            for (int j = 0; j < 8; j++)
                o[i + 1][j] += wr[0] * L[j] + wr[1] * m[j] + wr[2] * R[j];
        }
        if (i >= 0 && i < 8) {
            #pragma unroll
            for (int j = 0; j < 8; j++)
                o[i][j] += wr[3] * L[j] + wr[4] * m[j] + wr[5] * R[j];
        }
        if (i - 1 >= 0 && i - 1 < 8) {
            #pragma unroll
            for (int j = 0; j < 8; j++)
                o[i - 1][j] += wr[6] * L[j] + wr[7] * m[j] + wr[8] * R[j];
        }
    }

    float ss = 0.f;
    #pragma unroll
    for (int i = 0; i < 8; i++) {
        uint4 pv;
        pv.x = pack_h2(o[i][0], o[i][1]);
        pv.y = pack_h2(o[i][2], o[i][3]);
        pv.z = pack_h2(o[i][4], o[i][5]);
        pv.w = pack_h2(o[i][6], o[i][7]);
        *(uint4*)(op + (size_t)(y0 + i) * WID + x0) = pv;
        #pragma unroll
        for (int j = 0; j < 8; j++) ss += o[i][j] * o[i][j];
    }

    if (c < 2 * CC) {
        #pragma unroll
        for (int off = 16; off > 0; off >>= 1)
            ss += __shfl_down_sync(0xffffffffu, ss, off);
        if (lane == 0) g_sqp[bc][blockIdx.y * 8 + wp] = ss;
    }
}

// ---------------------------------------------------------------------------
__global__ __launch_bounds__(32) void sumsq_reduce_kernel()
{
    const int idx = blockIdx.x;             // b * 384 + c
    const int b = idx / (2 * CC);
    const int c = idx % (2 * CC);
    float v = g_sqp[b * C3 + c][threadIdx.x];
    #pragma unroll
    for (int off = 16; off > 0; off >>= 1)
        v += __shfl_down_sync(0xffffffffu, v, off);
    if (threadIdx.x == 0) g_sq[idx] = v;
}

// ---------------------------------------------------------------------------
// Split-K partials of S = Q @ K^T per (b,h) with fp16 MMA (m16n8k16).
// grid (NCHUNK, BB*NH), 256 threads. Tile = 128 px; warp w covers 16 px.
// ---------------------------------------------------------------------------
__global__ __launch_bounds__(256) void qk_partial_kernel()
{
    const int chunk = blockIdx.x;
    const int bh    = blockIdx.y;
    const int b  = bh >> 2;
    const int hh = bh & 3;

    const __half* qb = g_dwh + ((size_t)b * C3 + hh * DD) * HWS + (size_t)chunk * CHL;
    const __half* kb = qb + (size_t)CC * HWS;

    __shared__ unsigned qs[DD][68];
    __shared__ unsigned ks[DD][68];

    const int t    = threadIdx.x;
    const int lane = t & 31;
    const int w    = t >> 5;
    const int g    = lane >> 2;
    const int tg   = lane & 3;
    const int s0   = w * 8;

    float acc[3][6][4];
    #pragma unroll
    for (int mt = 0; mt < 3; mt++)
        #pragma unroll
        for (int nt = 0; nt < 6; nt++)
            #pragma unroll
            for (int i = 0; i < 4; i++) acc[mt][nt][i] = 0.f;

    for (int n0 = 0; n0 < CHL; n0 += 128) {
        #pragma unroll
        for (int i = 0; i < 3; i++) {
            int f  = t + i * 256;
            int cc = f >> 4;
            int cu = (f & 15) << 2;
            *(uint4*)&qs[cc][cu] = *(const uint4*)(qb + (size_t)cc * HWS + n0 + cu * 2);
            *(uint4*)&ks[cc][cu] = *(const uint4*)(kb + (size_t)cc * HWS + n0 + cu * 2);
        }
        __syncthreads();

        unsigned af[3][4], bf[6][2];
        #pragma unroll
        for (int mt = 0; mt < 3; mt++) {
            int m = mt * 16 + g;
            af[mt][0] = qs[m][s0 + tg];
            af[mt][1] = qs[m + 8][s0 + tg];
            af[mt][2] = qs[m][s0 + tg + 4];
            af[mt][3] = qs[m + 8][s0 + tg + 4];
        }
        #pragma unroll
        for (int nt = 0; nt < 6; nt++) {
            int n = nt * 8 + g;
            bf[nt][0] = ks[n][s0 + tg];
            bf[nt][1] = ks[n][s0 + tg + 4];
        }
        #pragma unroll
        for (int mt = 0; mt < 3; mt++)
            #pragma unroll
            for (int nt = 0; nt < 6; nt++)
                mma_fp16(acc[mt][nt], af[mt], bf[nt]);
        __syncthreads();
    }

    float* dst = g_part + ((size_t)(chunk * 8 + w) * (BB * NH) + bh) * (DD * DD);
    #pragma unroll
    for (int mt = 0; mt < 3; mt++) {
        #pragma unroll
        for (int nt = 0; nt < 6; nt++) {
            int row = mt * 16 + g;
            int col = nt * 8 + 2 * tg;
            *(float2*)(dst + row * DD + col)       = make_float2(acc[mt][nt][0], acc[mt][nt][1]);
            *(float2*)(dst + (row + 8) * DD + col) = make_float2(acc[mt][nt][2], acc[mt][nt][3]);
        }
    }
}

// ---------------------------------------------------------------------------
// Parallel reduction of Gram partials. grid 576, block 64.
// ---------------------------------------------------------------------------
__global__ __launch_bounds__(64) void part_reduce_kernel()
{
    const int idx = blockIdx.x * 64 + threadIdx.x;
    const int bh  = idx / (DD * DD);
    const int i   = idx % (DD * DD);
    float s = 0.f;
    #pragma unroll 8
    for (int ch = 0; ch < NPART; ch++)
        s += g_part[((size_t)ch * (BB * NH) + bh) * (DD * DD) + i];
    g_S[idx] = s;
}

// ---------------------------------------------------------------------------
// Scale -> softmax -> W2 = proj_w @ blockdiag(attn), emitted as fp16.
// ---------------------------------------------------------------------------
__global__ __launch_bounds__(192) void softmax_w2_kernel(
    const float* __restrict__ temp, const float* __restrict__ projw)
{
    const int bh = blockIdx.x;
    const int b  = bh >> 2;
    const int hh = bh & 3;
    const int t  = threadIdx.x;

    __shared__ float S[DD][DD];
    __shared__ float nq[DD], nk[DD];

    for (int i = t; i < DD * DD; i += 192)
        S[i / DD][i % DD] = g_S[bh * DD * DD + i];
    if (t < DD) {
        nq[t] = fmaxf(sqrtf(g_sq[b * 2 * CC + hh * DD + t]),      1e-12f);
        nk[t] = fmaxf(sqrtf(g_sq[b * 2 * CC + CC + hh * DD + t]), 1e-12f);
    }
    __syncthreads();

    const float tmp = temp[hh];
    for (int i = t; i < DD * DD; i += 192) {
        int d = i / DD, e = i % DD;
        S[d][e] = S[d][e] * tmp / (nq[d] * nk[e]);
    }
    __syncthreads();

    if (t < DD) {
        float mx = -1e30f;
        #pragma unroll
        for (int e = 0; e < DD; e++) mx = fmaxf(mx, S[t][e]);
        float sum = 0.f;
        #pragma unroll
        for (int e = 0; e < DD; e++) { float v = expf(S[t][e] - mx); S[t][e] = v; sum += v; }
        float inv = 1.f / sum;
        #pragma unroll
        for (int e = 0; e < DD; e++) S[t][e] *= inv;
    }
    __syncthreads();

    const int o = t;
    float pr[DD];
    #pragma unroll
    for (int d = 0; d < DD; d++) pr[d] = projw[o * CC + hh * DD + d];
    #pragma unroll 4
    for (int e = 0; e < DD; e++) {
        float s = 0.f;
        #pragma unroll
        for (int d = 0; d < DD; d++) s += pr[d] * S[d][e];
        g_w2h[((size_t)b * CC + o) * CC + hh * DD + e] = __float2half_rn(s);
    }
}

// ---------------------------------------------------------------------------
extern "C" void kernel_launch(void* const* d_in, const int* in_sizes, int n_in,
                              void* d_out, int out_size)
{
    const float* x      = (const float*)d_in[0];
    const float* qkv_w  = (const float*)d_in[1];
    const float* dw_w   = (const float*)d_in[2];
    const float* temp   = (const float*)d_in[3];
    const float* proj_w = (const float*)d_in[4];
    float* out = (float*)d_out;

    __half *wqh_buf, *qkvh_buf, *dwh_buf, *w2h_buf;
    cudaGetSymbolAddress((void**)&wqh_buf,  g_wqh);
    cudaGetSymbolAddress((void**)&qkvh_buf, g_qkvh);
    cudaGetSymbolAddress((void**)&dwh_buf,  g_dwh);
    cudaGetSymbolAddress((void**)&w2h_buf,  g_w2h);

    // 2 no-ops; wq2h is 3rd, gemm1 lands in ncu's profiled 4th slot
    noop_kernel<<<1, 32>>>();
    noop_kernel<<<1, 32>>>();

    // 0) qkv_w -> fp16 (tiny; identical rounding to old in-loop cvt)
    wq2h_kernel<<<(C3 * CC) / (256 * 4), 256>>>(qkv_w);

    // 1) qkv 1x1 conv: 96x256 blocks, A fp16 weights, B = x f32 direct
    gemm96_kernel<float, __half, CC><<<dim3(C3 / 96, HWS / 256, BB), 256>>>(
        wqh_buf, x, qkvh_buf, C3, HWS,
        0L, (long)CC * HWS, (long)C3 * HWS);

    // 2) depthwise 3x3 v5 (warp-row, vectorized)
    dwconv_kernel<<<dim3(1, 4, BB * C3), 256>>>(dw_w);

    // 3) finish ||q||^2, ||k||^2
    sumsq_reduce_kernel<<<BB * 2 * CC, 32>>>();

    // 4) split-K S = Q K^T partials (fp16 MMA)
    qk_partial_kernel<<<dim3(NCHUNK, BB * NH), 256>>>();

    // 5) parallel Gram reduce
    part_reduce_kernel<<<576, 64>>>();

    // 6) scale + softmax + W2 (fp16 out)
    softmax_w2_kernel<<<BB * NH, 192>>>(temp, proj_w);

    // 7) fused (attn @ v) + proj: 96x256 blocks, A fp16, B fp16, C f32
    gemm96_kernel<__half, float, CC><<<dim3(CC / 96, HWS / 256, BB), 256>>>(
        w2h_buf, dwh_buf + (size_t)2 * CC * HWS, out, CC, HWS,
        (long)CC * CC, (long)C3 * HWS, (long)CC * HWS);
}

// round 15
// speedup vs baseline: 1.2091x; 1.2091x over previous
#include <cuda_runtime.h>
#include <cuda_fp16.h>
#include <type_traits>

// Problem constants
#define BB   4
#define CC   192
#define C3   576
#define HGT  256
#define WID  256
#define HWS  65536
#define NH   4
#define DD   48
#define NCHUNK 32
#define CHL  (HWS / NCHUNK)   // 2048
#define NPART (NCHUNK * 8)    // 256 split-K partial slots

// Scratch (device globals)
__device__ __half g_wqh [C3 * CC];                // qkv_w in fp16
__device__ __half g_qkvh[(size_t)BB * C3 * HWS];  // 1x1 conv output (fp16)
__device__ __half g_dwh [(size_t)BB * C3 * HWS];  // dwconv output (fp16)
__device__ float  g_sqp[BB * C3][64];             // dwconv sumsq partials
__device__ float  g_sq [BB * 2 * CC];
__device__ float  g_part[(size_t)NPART * BB * NH * DD * DD];
__device__ float  g_S  [16 * DD * DD];            // reduced Gram
__device__ __half g_w2h[BB * CC * CC];            // fused proj @ attn, fp16

// ---------------------------------------------------------------------------
__device__ __forceinline__ unsigned pack_h2(float lo, float hi) {
    __half2 h = __halves2half2(__float2half_rn(lo), __float2half_rn(hi));
    return *(unsigned*)&h;
}

__device__ __forceinline__ void mma_fp16(float c[4], const unsigned a[4], const unsigned b[2]) {
    asm volatile(
        "mma.sync.aligned.m16n8k16.row.col.f32.f16.f16.f32 "
        "{%0,%1,%2,%3}, {%4,%5,%6,%7}, {%8,%9}, {%0,%1,%2,%3};"
        : "+f"(c[0]), "+f"(c[1]), "+f"(c[2]), "+f"(c[3])
        : "r"(a[0]), "r"(a[1]), "r"(a[2]), "r"(a[3]), "r"(b[0]), "r"(b[1]));
}

// no-op kernel: shifts subsequent launches into ncu's profiled (4th) slot
__global__ void noop_kernel() {}

// ---------------------------------------------------------------------------
// qkv_w (f32) -> fp16, identical rounding to the old in-GEMM cvt. 4/thread.
// ---------------------------------------------------------------------------
__global__ __launch_bounds__(256) void wq2h_kernel(const float* __restrict__ w)
{
    const int i = (blockIdx.x * 256 + threadIdx.x) * 4;
    float4 a = *(const float4*)(w + i);
    uint2 p;
    p.x = pack_h2(a.x, a.y);
    p.y = pack_h2(a.z, a.w);
    *(uint2*)(g_wqh + i) = p;
}

// ---------------------------------------------------------------------------
// Tensor-core GEMM (R13, proven): C[M,N](CT) = A[M,K](half) @ B[K,N](BT).
// BM=64, BN=256, BK=16 (one m16n8k16 step), 256 threads, batch via grid.z.
// PD=1 for f32 B (register budget; B strips are L2-hits for the co-resident
// sharing CTAs), 2 for fp16 B. Fully unrolled (K compile-time).
// Conflict-free smem (strides ≡ 8 mod 32).
// ---------------------------------------------------------------------------
struct BStageF { float4 v[4]; };
struct BStageH { uint2  v[4]; };

template <typename BT, typename CT, int K>
__global__ __launch_bounds__(256, 2) void gemm_h_kernel(
    const __half* __restrict__ A, const BT* __restrict__ B, CT* __restrict__ C,
    int M, int N, long sA, long sB, long sC)
{
    constexpr int NT = K >> 4;                       // 12
    constexpr bool BF32 = (sizeof(BT) == 4);
    constexpr int PD = BF32 ? 1 : 2;                 // prefetch distance

    __shared__ unsigned Ap[2][8][64 + 8];
    __shared__ unsigned Bp[2][8][256 + 8];

    const __half* Ab = A + (long)blockIdx.z * sA;
    const BT*     Bb = B + (long)blockIdx.z * sB;
    CT*           Cb = C + (long)blockIdx.z * sC;

    const int m0 = blockIdx.x * 64;
    const int n0 = blockIdx.y * 256;
    const int t    = threadIdx.x;
    const int lane = t & 31;
    const int wid  = t >> 5;
    const int wm   = (wid & 1) * 32;
    const int wn   = (wid >> 1) * 64;
    const int g    = lane >> 2;
    const int tg   = lane & 3;

    float acc[2][8][4];
    #pragma unroll
    for (int mt = 0; mt < 2; mt++)
        #pragma unroll
        for (int nt = 0; nt < 8; nt++)
            #pragma unroll
            for (int i = 0; i < 4; i++) acc[mt][nt][i] = 0.f;

    const int am  = t >> 2;            // A row 0..63
    const int ak  = (t & 3) << 2;      // A col: 0,4,8,12
    const int ak2 = ak >> 1;
    const int bn4 = (t & 63) << 2;     // B col 0..252
    const int bk2 = (t >> 6) << 1;     // packed k2 base: 0,2,4,6

    const __half* apt = Ab + (long)(m0 + am) * K + ak;
    const BT*     bpt = Bb + (long)(bk2 * 2) * N + n0 + bn4;

    uint2 pa[PD];
    using BS = typename std::conditional<BF32, BStageF, BStageH>::type;
    BS pb[PD];

    auto ldg_tile = [&](int kt, int s) {
        const __half* ap = apt + kt * 16;
        const BT*     bp = bpt + (long)kt * 16 * N;
        pa[s] = *(const uint2*)ap;
        #pragma unroll
        for (int i = 0; i < 4; i++) {
            if constexpr (BF32) pb[s].v[i] = *(const float4*)(bp + (long)i * N);
            else                pb[s].v[i] = *(const uint2*) (bp + (long)i * N);
        }
    };

    auto sts_tile = [&](int s, int stage) {
        Ap[stage][ak2 + 0][am] = pa[s].x;
        Ap[stage][ak2 + 1][am] = pa[s].y;
        uint4 u0, u1;
        if constexpr (BF32) {
            u0.x = pack_h2(pb[s].v[0].x, pb[s].v[1].x);
            u0.y = pack_h2(pb[s].v[0].y, pb[s].v[1].y);
            u0.z = pack_h2(pb[s].v[0].z, pb[s].v[1].z);
            u0.w = pack_h2(pb[s].v[0].w, pb[s].v[1].w);
            u1.x = pack_h2(pb[s].v[2].x, pb[s].v[3].x);
            u1.y = pack_h2(pb[s].v[2].y, pb[s].v[3].y);
            u1.z = pack_h2(pb[s].v[2].z, pb[s].v[3].z);
            u1.w = pack_h2(pb[s].v[2].w, pb[s].v[3].w);
        } else {
            u0.x = __byte_perm(pb[s].v[0].x, pb[s].v[1].x, 0x5410);
            u0.y = __byte_perm(pb[s].v[0].x, pb[s].v[1].x, 0x7632);
            u0.z = __byte_perm(pb[s].v[0].y, pb[s].v[1].y, 0x5410);
            u0.w = __byte_perm(pb[s].v[0].y, pb[s].v[1].y, 0x7632);
            u1.x = __byte_perm(pb[s].v[2].x, pb[s].v[3].x, 0x5410);
            u1.y = __byte_perm(pb[s].v[2].x, pb[s].v[3].x, 0x7632);
            u1.z = __byte_perm(pb[s].v[2].y, pb[s].v[3].y, 0x5410);
            u1.w = __byte_perm(pb[s].v[2].y, pb[s].v[3].y, 0x7632);
        }
        *(uint4*)&Bp[stage][bk2][bn4]     = u0;
        *(uint4*)&Bp[stage][bk2 + 1][bn4] = u1;
    };

    // prologue
    ldg_tile(0, 0);
    sts_tile(0, 0);
    if constexpr (PD == 2) ldg_tile(1, 1);
    __syncthreads();

    #pragma unroll
    for (int kt = 0; kt < NT; kt++) {
        const int cur = kt & 1;

        if (kt + PD < NT) ldg_tile(kt + PD, (kt + PD) % PD);

        unsigned af[2][4], bf[8][2];
        #pragma unroll
        for (int mt = 0; mt < 2; mt++) {
            int mb = wm + mt * 16 + g;
            af[mt][0] = Ap[cur][tg][mb];
            af[mt][1] = Ap[cur][tg][mb + 8];
            af[mt][2] = Ap[cur][tg + 4][mb];
            af[mt][3] = Ap[cur][tg + 4][mb + 8];
        }
        #pragma unroll
        for (int nt = 0; nt < 8; nt++) {
            int nb = wn + nt * 8 + g;
            bf[nt][0] = Bp[cur][tg][nb];
            bf[nt][1] = Bp[cur][tg + 4][nb];
        }
        #pragma unroll
        for (int mt = 0; mt < 2; mt++)
            #pragma unroll
            for (int nt = 0; nt < 8; nt++)
                mma_fp16(acc[mt][nt], af[mt], bf[nt]);

        if (kt + 1 < NT) sts_tile((kt + 1) % PD, cur ^ 1);
        __syncthreads();
    }

    #pragma unroll
    for (int mt = 0; mt < 2; mt++) {
        #pragma unroll
        for (int nt = 0; nt < 8; nt++) {
            int row = m0 + wm + mt * 16 + g;
            int col = n0 + wn + nt * 8 + 2 * tg;
            if constexpr (sizeof(CT) == 2) {
                *(unsigned*)((__half*)Cb + (long)row * N + col) =
                    pack_h2(acc[mt][nt][0], acc[mt][nt][1]);
                *(unsigned*)((__half*)Cb + (long)(row + 8) * N + col) =
                    pack_h2(acc[mt][nt][2], acc[mt][nt][3]);
            } else {
                *(float2*)((float*)Cb + (long)row * N + col) =
                    make_float2(acc[mt][nt][0], acc[mt][nt][1]);
                *(float2*)((float*)Cb + (long)(row + 8) * N + col) =
                    make_float2(acc[mt][nt][2], acc[mt][nt][3]);
            }
        }
    }
}

// ---------------------------------------------------------------------------
// Depthwise 3x3 conv v6: warp covers a full 256-px row (8 px/lane, LDG.128),
// 4 output rows per warp (6 input rows) -> ~70 regs -> 3 CTAs/SM.
// x-halo via 2 warp shuffles; fp32 math; fused sumsq.
// grid (1, 8, BB*C3), block 256 (8 warps x 4 rows = 32 rows per block).
// ---------------------------------------------------------------------------
__global__ __launch_bounds__(256) void dwconv_kernel(const float* __restrict__ w)
{
    const int bc = blockIdx.z;
    const int c  = bc % C3;
    const __half* plane = g_qkvh + (size_t)bc * HWS;
    __half*       op    = g_dwh  + (size_t)bc * HWS;

    float wr[9];
    #pragma unroll
    for (int i = 0; i < 9; i++) wr[i] = w[c * 9 + i];

    const int t    = threadIdx.x;
    const int lane = t & 31;
    const int wp   = t >> 5;
    const int y0   = blockIdx.y * 32 + wp * 4;
    const int x0   = lane * 8;

    float o[4][8];
    #pragma unroll
    for (int i = 0; i < 4; i++)
        #pragma unroll
        for (int j = 0; j < 8; j++) o[i][j] = 0.f;

    #pragma unroll
    for (int i = -1; i <= 4; i++) {
        const int r = y0 + i;
        float m[8];
        if (r >= 0 && r < HGT) {
            uint4 v = *(const uint4*)(plane + (size_t)r * WID + x0);
            float2 f;
            f = __half22float2(*(__half2*)&v.x); m[0] = f.x; m[1] = f.y;
            f = __half22float2(*(__half2*)&v.y); m[2] = f.x; m[3] = f.y;
            f = __half22float2(*(__half2*)&v.z); m[4] = f.x; m[5] = f.y;
            f = __half22float2(*(__half2*)&v.w); m[6] = f.x; m[7] = f.y;
        } else {
            #pragma unroll
            for (int j = 0; j < 8; j++) m[j] = 0.f;
        }
        float lh = __shfl_up_sync(0xffffffffu,  m[7], 1);
        float rh = __shfl_down_sync(0xffffffffu, m[0], 1);
        if (lane == 0)  lh = 0.f;
        if (lane == 31) rh = 0.f;

        float L[8], R[8];
        L[0] = lh;
        #pragma unroll
        for (int j = 1; j < 8; j++) L[j] = m[j - 1];
        #pragma unroll
        for (int j = 0; j < 7; j++) R[j] = m[j + 1];
        R[7] = rh;

        if (i + 1 >= 0 && i + 1 < 4) {      // top weight row -> output row r+1
            #pragma unroll
            for (int j = 0; j < 8; j++)
                o[i + 1][j] += wr[0] * L[j] + wr[1] * m[j] + wr[2] * R[j];
        }
        if (i >= 0 && i < 4) {              // middle -> output row r
            #pragma unroll
            for (int j = 0; j < 8; j++)
                o[i][j] += wr[3] * L[j] + wr[4] * m[j] + wr[5] * R[j];
        }
        if (i - 1 >= 0 && i - 1 < 4) {      // bottom -> output row r-1
            #pragma unroll
            for (int j = 0; j < 8; j++)
                o[i - 1][j] += wr[6] * L[j] + wr[7] * m[j] + wr[8] * R[j];
        }
    }

    float ss = 0.f;
    #pragma unroll
    for (int i = 0; i < 4; i++) {
        uint4 pv;
        pv.x = pack_h2(o[i][0], o[i][1]);
        pv.y = pack_h2(o[i][2], o[i][3]);
        pv.z = pack_h2(o[i][4], o[i][5]);
        pv.w = pack_h2(o[i][6], o[i][7]);
        *(uint4*)(op + (size_t)(y0 + i) * WID + x0) = pv;
        #pragma unroll
        for (int j = 0; j < 8; j++) ss += o[i][j] * o[i][j];
    }

    if (c < 2 * CC) {
        #pragma unroll
        for (int off = 16; off > 0; off >>= 1)
            ss += __shfl_down_sync(0xffffffffu, ss, off);
        if (lane == 0) g_sqp[bc][blockIdx.y * 8 + wp] = ss;
    }
}

// ---------------------------------------------------------------------------
// Combined reduction: blocks [0,576) reduce Gram partials (64 thr each);
// blocks [576,600) finish sumsq (64 thr, one channel per thread, 64 partials).
// ---------------------------------------------------------------------------
__global__ __launch_bounds__(64) void reduce_kernel()
{
    if (blockIdx.x < 576) {
        const int idx = blockIdx.x * 64 + threadIdx.x;  // 0..36863
        const int bh  = idx / (DD * DD);
        const int i   = idx % (DD * DD);
        float s = 0.f;
        #pragma unroll 8
        for (int ch = 0; ch < NPART; ch++)
            s += g_part[((size_t)ch * (BB * NH) + bh) * (DD * DD) + i];
        g_S[idx] = s;
    } else {
        const int idx = (blockIdx.x - 576) * 64 + threadIdx.x;  // 0..1535
        const int b = idx / (2 * CC);
        const int c = idx % (2 * CC);
        const float* p = g_sqp[b * C3 + c];
        float s = 0.f;
        #pragma unroll 8
        for (int j = 0; j < 64; j++) s += p[j];
        g_sq[idx] = s;
    }
}

// ---------------------------------------------------------------------------
// Split-K partials of S = Q @ K^T per (b,h) with fp16 MMA (m16n8k16).
// grid (NCHUNK, BB*NH), 256 threads. Tile = 128 px; warp w covers 16 px.
// ---------------------------------------------------------------------------
__global__ __launch_bounds__(256) void qk_partial_kernel()
{
    const int chunk = blockIdx.x;
    const int bh    = blockIdx.y;
    const int b  = bh >> 2;
    const int hh = bh & 3;

    const __half* qb = g_dwh + ((size_t)b * C3 + hh * DD) * HWS + (size_t)chunk * CHL;
    const __half* kb = qb + (size_t)CC * HWS;

    __shared__ unsigned qs[DD][68];
    __shared__ unsigned ks[DD][68];

    const int t    = threadIdx.x;
    const int lane = t & 31;
    const int w    = t >> 5;
    const int g    = lane >> 2;
    const int tg   = lane & 3;
    const int s0   = w * 8;

    float acc[3][6][4];
    #pragma unroll
    for (int mt = 0; mt < 3; mt++)
        #pragma unroll
        for (int nt = 0; nt < 6; nt++)
            #pragma unroll
            for (int i = 0; i < 4; i++) acc[mt][nt][i] = 0.f;

    for (int n0 = 0; n0 < CHL; n0 += 128) {
        #pragma unroll
        for (int i = 0; i < 3; i++) {
            int f  = t + i * 256;
            int cc = f >> 4;
            int cu = (f & 15) << 2;
            *(uint4*)&qs[cc][cu] = *(const uint4*)(qb + (size_t)cc * HWS + n0 + cu * 2);
            *(uint4*)&ks[cc][cu] = *(const uint4*)(kb + (size_t)cc * HWS + n0 + cu * 2);
        }
        __syncthreads();

        unsigned af[3][4], bf[6][2];
        #pragma unroll
        for (int mt = 0; mt < 3; mt++) {
            int m = mt * 16 + g;
            af[mt][0] = qs[m][s0 + tg];
            af[mt][1] = qs[m + 8][s0 + tg];
            af[mt][2] = qs[m][s0 + tg + 4];
            af[mt][3] = qs[m + 8][s0 + tg + 4];
        }
        #pragma unroll
        for (int nt = 0; nt < 6; nt++) {
            int n = nt * 8 + g;
            bf[nt][0] = ks[n][s0 + tg];
            bf[nt][1] = ks[n][s0 + tg + 4];
        }
        #pragma unroll
        for (int mt = 0; mt < 3; mt++)
            #pragma unroll
            for (int nt = 0; nt < 6; nt++)
                mma_fp16(acc[mt][nt], af[mt], bf[nt]);
        __syncthreads();
    }

    float* dst = g_part + ((size_t)(chunk * 8 + w) * (BB * NH) + bh) * (DD * DD);
    #pragma unroll
    for (int mt = 0; mt < 3; mt++) {
        #pragma unroll
        for (int nt = 0; nt < 6; nt++) {
            int row = mt * 16 + g;
            int col = nt * 8 + 2 * tg;
            *(float2*)(dst + row * DD + col)       = make_float2(acc[mt][nt][0], acc[mt][nt][1]);
            *(float2*)(dst + (row + 8) * DD + col) = make_float2(acc[mt][nt][2], acc[mt][nt][3]);
        }
    }
}

// ---------------------------------------------------------------------------
// Scale -> softmax -> W2 = proj_w @ blockdiag(attn), emitted as fp16.
// ---------------------------------------------------------------------------
__global__ __launch_bounds__(192) void softmax_w2_kernel(
    const float* __restrict__ temp, const float* __restrict__ projw)
{
    const int bh = blockIdx.x;
    const int b  = bh >> 2;
    const int hh = bh & 3;
    const int t  = threadIdx.x;

    __shared__ float S[DD][DD];
    __shared__ float nq[DD], nk[DD];

    for (int i = t; i < DD * DD; i += 192)
        S[i / DD][i % DD] = g_S[bh * DD * DD + i];
    if (t < DD) {
        nq[t] = fmaxf(sqrtf(g_sq[b * 2 * CC + hh * DD + t]),      1e-12f);
        nk[t] = fmaxf(sqrtf(g_sq[b * 2 * CC + CC + hh * DD + t]), 1e-12f);
    }
    __syncthreads();

    const float tmp = temp[hh];
    for (int i = t; i < DD * DD; i += 192) {
        int d = i / DD, e = i % DD;
        S[d][e] = S[d][e] * tmp / (nq[d] * nk[e]);
    }
    __syncthreads();

    if (t < DD) {
        float mx = -1e30f;
        #pragma unroll
        for (int e = 0; e < DD; e++) mx = fmaxf(mx, S[t][e]);
        float sum = 0.f;
        #pragma unroll
        for (int e = 0; e < DD; e++) { float v = expf(S[t][e] - mx); S[t][e] = v; sum += v; }
        float inv = 1.f / sum;
        #pragma unroll
        for (int e = 0; e < DD; e++) S[t][e] *= inv;
    }
    __syncthreads();

    const int o = t;
    float pr[DD];
    #pragma unroll
    for (int d = 0; d < DD; d++) pr[d] = projw[o * CC + hh * DD + d];
    #pragma unroll 4
    for (int e = 0; e < DD; e++) {
        float s = 0.f;
        #pragma unroll
        for (int d = 0; d < DD; d++) s += pr[d] * S[d][e];
        g_w2h[((size_t)b * CC + o) * CC + hh * DD + e] = __float2half_rn(s);
    }
}

// ---------------------------------------------------------------------------
extern "C" void kernel_launch(void* const* d_in, const int* in_sizes, int n_in,
                              void* d_out, int out_size)
{
    const float* x      = (const float*)d_in[0];
    const float* qkv_w  = (const float*)d_in[1];
    const float* dw_w   = (const float*)d_in[2];
    const float* temp   = (const float*)d_in[3];
    const float* proj_w = (const float*)d_in[4];
    float* out = (float*)d_out;

    __half *wqh_buf, *qkvh_buf, *dwh_buf, *w2h_buf;
    cudaGetSymbolAddress((void**)&wqh_buf,  g_wqh);
    cudaGetSymbolAddress((void**)&qkvh_buf, g_qkvh);
    cudaGetSymbolAddress((void**)&dwh_buf,  g_dwh);
    cudaGetSymbolAddress((void**)&w2h_buf,  g_w2h);

    // 1 no-op; dwconv lands in ncu's profiled 4th slot
    noop_kernel<<<1, 32>>>();

    // 0) qkv_w -> fp16 (tiny; identical rounding to old in-loop cvt)
    wq2h_kernel<<<(C3 * CC) / (256 * 4), 256>>>(qkv_w);

    // 1) qkv 1x1 conv: 64x256 blocks (R13), A fp16 weights, B = x f32 direct
    gemm_h_kernel<float, __half, CC><<<dim3(C3 / 64, HWS / 256, BB), 256>>>(
        wqh_buf, x, qkvh_buf, C3, HWS,
        0L, (long)CC * HWS, (long)C3 * HWS);

    // 2) depthwise 3x3 v6 (4 rows/warp, higher occupancy)   <-- profiled
    dwconv_kernel<<<dim3(1, 8, BB * C3), 256>>>(dw_w);

    // 3) split-K S = Q K^T partials (fp16 MMA)
    qk_partial_kernel<<<dim3(NCHUNK, BB * NH), 256>>>();

    // 4) combined: Gram partial reduce + sumsq finish
    reduce_kernel<<<600, 64>>>();

    // 5) scale + softmax + W2 (fp16 out)
    softmax_w2_kernel<<<BB * NH, 192>>>(temp, proj_w);

    // 6) fused (attn @ v) + proj: 64x256 blocks, A fp16, B fp16, C f32
    gemm_h_kernel<__half, float, CC><<<dim3(CC / 64, HWS / 256, BB), 256>>>(
        w2h_buf, dwh_buf + (size_t)2 * CC * HWS, out, CC, HWS,
        (long)CC * CC, (long)C3 * HWS, (long)CC * HWS);
}